// round 7
// baseline (speedup 1.0000x reference)
#include <cuda_runtime.h>
#include <cuda_bf16.h>
#include <cstdint>
#include <math.h>

#define NROWS 4096
#define DDIM  512
#define BM 128
#define BN 128
#define BK 32
#define NT   (NROWS / BM)            // 32
#define NBLK (NT * (NT + 1) / 2)     // 528
#define NCH  (DDIM / BK)             // 16
#define LDSW 40                      // smem row stride (bf16) -> conflict-free ldmatrix
#define STAGE_ELEMS (BM * LDSW)      // per array per stage
#define STAGE_BYTES (2 * STAGE_ELEMS * 2)      // A+B, bytes (20480)
#define SMEM_TOTAL  (3 * STAGE_BYTES)          // 61440

__device__ __nv_bfloat16 g_xb[NROWS * DDIM];   // 4 MB bf16 copy of x
__device__ float g_norms[NROWS];

#define LDSM_X4(r, addr)                                                        \
    asm volatile("ldmatrix.sync.aligned.m8n8.x4.shared.b16 {%0,%1,%2,%3}, [%4];"\
        : "=r"((r)[0]), "=r"((r)[1]), "=r"((r)[2]), "=r"((r)[3]) : "r"(addr))
#define MMA16816(c, a, b0, b1)                                                  \
    asm volatile("mma.sync.aligned.m16n8k16.row.col.f32.bf16.bf16.f32 "         \
        "{%0,%1,%2,%3}, {%4,%5,%6,%7}, {%8,%9}, {%0,%1,%2,%3};"                 \
        : "+f"((c)[0]), "+f"((c)[1]), "+f"((c)[2]), "+f"((c)[3])                \
        : "r"((a)[0]), "r"((a)[1]), "r"((a)[2]), "r"((a)[3]),                   \
          "r"(b0), "r"(b1))
#define CP_ASYNC16(dst, src)                                                    \
    asm volatile("cp.async.cg.shared.global [%0], [%1], 16;"                    \
        :: "r"(dst), "l"(src))

// ---------------------------------------------------------------------------
// Prep: fp32 norms + bf16 conversion. One warp per row.
// ---------------------------------------------------------------------------
__global__ __launch_bounds__(256) void prep_kernel(const float* __restrict__ x) {
    int row  = blockIdx.x * 8 + (threadIdx.x >> 5);
    int lane = threadIdx.x & 31;
    const float4* xr = reinterpret_cast<const float4*>(x + (size_t)row * DDIM);
    uint2* xo = reinterpret_cast<uint2*>(g_xb + (size_t)row * DDIM);
    float s = 0.f;
#pragma unroll
    for (int k = 0; k < 4; k++) {
        int idx = lane + k * 32;
        float4 v = xr[idx];
        s += v.x * v.x + v.y * v.y + v.z * v.z + v.w * v.w;
        __nv_bfloat162 p0 = __float22bfloat162_rn(make_float2(v.x, v.y));
        __nv_bfloat162 p1 = __float22bfloat162_rn(make_float2(v.z, v.w));
        uint2 o;
        o.x = *reinterpret_cast<uint32_t*>(&p0);
        o.y = *reinterpret_cast<uint32_t*>(&p1);
        xo[idx] = o;
    }
#pragma unroll
    for (int o = 16; o; o >>= 1) s += __shfl_xor_sync(0xffffffffu, s, o);
    if (lane == 0) g_norms[row] = s;
}

// ---------------------------------------------------------------------------
// Dist: 128x128 CTA tile, 4 warps x (64x64), 3-stage cp.async pipeline
// ---------------------------------------------------------------------------
__global__ __launch_bounds__(128, 2) void dist_kernel(float* __restrict__ out) {
    extern __shared__ __align__(16) char sm[];

    int tid  = threadIdx.x;
    int lane = tid & 31;
    int wid  = tid >> 5;
    int wr   = wid >> 1;     // warp row 0..1 (64 rows)
    int wc   = wid & 1;      // warp col 0..1 (64 cols)

    // linear block id -> (bi, bj), bj <= bi
    int t  = blockIdx.x;
    int bi = (int)((sqrtf(8.0f * (float)t + 1.0f) - 1.0f) * 0.5f);
    while ((bi * (bi + 1)) / 2 > t)        bi--;
    while (((bi + 1) * (bi + 2)) / 2 <= t) bi++;
    int bj = t - (bi * (bi + 1)) / 2;
    int i0 = bi * BM;
    int j0 = bj * BN;

    const __nv_bfloat16* gA = g_xb + (size_t)i0 * DDIM;
    const __nv_bfloat16* gB = g_xb + (size_t)j0 * DDIM;

    float acc[4][8][4];
#pragma unroll
    for (int m = 0; m < 4; m++)
#pragma unroll
        for (int n = 0; n < 8; n++)
#pragma unroll
            for (int e = 0; e < 4; e++) acc[m][n][e] = 0.f;

    // cp.async coords: 128 threads; per array 512 x 16B -> 4 iters
    int r_ld = tid >> 2;         // 0..31
    int q_ld = tid & 3;          // 16B segment within 64B row chunk

    auto stageA = [&](int s) -> char* { return sm + s * STAGE_BYTES; };
    auto stageB = [&](int s) -> char* { return sm + s * STAGE_BYTES + STAGE_ELEMS * 2; };

    auto issue = [&](int c) {
        int s  = c % 3;
        int kb = c * BK;
        char* a = stageA(s);
        char* b = stageB(s);
#pragma unroll
        for (int it = 0; it < 4; it++) {
            int r = r_ld + it * 32;
            uint32_t da = (uint32_t)__cvta_generic_to_shared(
                a + (r * LDSW + q_ld * 8) * 2);
            CP_ASYNC16(da, gA + (size_t)r * DDIM + kb + q_ld * 8);
            uint32_t db = (uint32_t)__cvta_generic_to_shared(
                b + (r * LDSW + q_ld * 8) * 2);
            CP_ASYNC16(db, gB + (size_t)r * DDIM + kb + q_ld * 8);
        }
        asm volatile("cp.async.commit_group;");
    };

    // ldmatrix per-thread offsets
    // A x4: rows m_base + (lane&15), k half (lane>>4)*8
    int arow = wr * 64 + (lane & 15);
    int akof = (lane >> 4) * 8;
    // B x4 (n16 x k16): row n_base + ((lane>>4)&1)*8 + (lane&7), k + ((lane>>3)&1)*8
    int brow = wc * 64 + ((lane >> 4) & 1) * 8 + (lane & 7);
    int bkof = ((lane >> 3) & 1) * 8;

    issue(0);
    issue(1);

    for (int c = 0; c < NCH; c++) {
        if (c + 1 < NCH) {
            asm volatile("cp.async.wait_group 1;");
        } else {
            asm volatile("cp.async.wait_group 0;");
        }
        __syncthreads();
        if (c + 2 < NCH) issue(c + 2);

        int s = c % 3;
        uint32_t aBase = (uint32_t)__cvta_generic_to_shared(stageA(s));
        uint32_t bBase = (uint32_t)__cvta_generic_to_shared(stageB(s));
#pragma unroll
        for (int ks = 0; ks < 2; ks++) {
            uint32_t afr[4][4], bfr[4][4];
#pragma unroll
            for (int mi = 0; mi < 4; mi++) {
                uint32_t ad = aBase +
                    (uint32_t)(((arow + mi * 16) * LDSW + ks * 16 + akof) * 2);
                LDSM_X4(afr[mi], ad);
            }
#pragma unroll
            for (int p = 0; p < 4; p++) {
                uint32_t bd = bBase +
                    (uint32_t)(((brow + p * 16) * LDSW + ks * 16 + bkof) * 2);
                LDSM_X4(bfr[p], bd);
            }
#pragma unroll
            for (int mi = 0; mi < 4; mi++)
#pragma unroll
                for (int p = 0; p < 4; p++) {
                    MMA16816(acc[mi][2 * p],     afr[mi], bfr[p][0], bfr[p][1]);
                    MMA16816(acc[mi][2 * p + 1], afr[mi], bfr[p][2], bfr[p][3]);
                }
        }
    }

    // Epilogue: c-frag map: rows trow, trow+8; cols tcol, tcol+1
    int trow = lane >> 2;
    int tcol = (lane & 3) * 2;
#pragma unroll
    for (int mi = 0; mi < 4; mi++) {
#pragma unroll
        for (int half = 0; half < 2; half++) {
            int i = i0 + wr * 64 + mi * 16 + half * 8 + trow;
            float ni_ = g_norms[i];
            int ib = (i * (i - 1)) >> 1;
#pragma unroll
            for (int nj = 0; nj < 8; nj++) {
                int j = j0 + wc * 64 + nj * 8 + tcol;
                float c0 = acc[mi][nj][half * 2 + 0];
                float c1 = acc[mi][nj][half * 2 + 1];
                if (j < i)
                    out[ib + j] =
                        sqrtf(fmaxf(ni_ + g_norms[j] - 2.0f * c0, 0.0f));
                if (j + 1 < i)
                    out[ib + j + 1] =
                        sqrtf(fmaxf(ni_ + g_norms[j + 1] - 2.0f * c1, 0.0f));
            }
        }
    }
}

extern "C" void kernel_launch(void* const* d_in, const int* in_sizes, int n_in,
                              void* d_out, int out_size) {
    const float* x = (const float*)d_in[0];
    float* out = (float*)d_out;
    (void)in_sizes; (void)n_in; (void)out_size;

    prep_kernel<<<NROWS / 8, 256>>>(x);

    cudaFuncSetAttribute(dist_kernel, cudaFuncAttributeMaxDynamicSharedMemorySize,
                         SMEM_TOTAL);
    dist_kernel<<<NBLK, 128, SMEM_TOTAL>>>(out);
}

// round 11
// speedup vs baseline: 1.1807x; 1.1807x over previous
#include <cuda_runtime.h>
#include <cuda_bf16.h>
#include <cstdint>
#include <math.h>

#define NROWS 4096
#define DDIM  512
#define BM 128
#define BN 128
#define BK 64
#define NT   (NROWS / BM)            // 32
#define NBLK (NT * (NT + 1) / 2)     // 528
#define NCH  (DDIM / BK)             // 8
#define LDSW 72                      // smem row stride (bf16): 144B = 9*16B -> conflict-free
#define STAGE_ELEMS (BM * LDSW)                 // per array per stage (9216)
#define STAGE_BYTES (2 * STAGE_ELEMS * 2)       // A+B bytes (36864)
#define NSTAGE 3
#define SMEM_TOTAL  (NSTAGE * STAGE_BYTES)      // 110592

__device__ __nv_bfloat16 g_xb[NROWS * DDIM];   // 4 MB bf16 copy of x
__device__ float g_norms[NROWS];

#define LDSM_X4(r, addr)                                                        \
    asm volatile("ldmatrix.sync.aligned.m8n8.x4.shared.b16 {%0,%1,%2,%3}, [%4];"\
        : "=r"((r)[0]), "=r"((r)[1]), "=r"((r)[2]), "=r"((r)[3]) : "r"(addr))
#define MMA16816(c, a, b0, b1)                                                  \
    asm volatile("mma.sync.aligned.m16n8k16.row.col.f32.bf16.bf16.f32 "         \
        "{%0,%1,%2,%3}, {%4,%5,%6,%7}, {%8,%9}, {%0,%1,%2,%3};"                 \
        : "+f"((c)[0]), "+f"((c)[1]), "+f"((c)[2]), "+f"((c)[3])                \
        : "r"((a)[0]), "r"((a)[1]), "r"((a)[2]), "r"((a)[3]),                   \
          "r"(b0), "r"(b1))
#define CP_ASYNC16(dst, src)                                                    \
    asm volatile("cp.async.cg.shared.global [%0], [%1], 16;"                    \
        :: "r"(dst), "l"(src))

// ---------------------------------------------------------------------------
// Prep: fp32 norms + bf16 conversion. One warp per row.
// ---------------------------------------------------------------------------
__global__ __launch_bounds__(256) void prep_kernel(const float* __restrict__ x) {
    int row  = blockIdx.x * 8 + (threadIdx.x >> 5);
    int lane = threadIdx.x & 31;
    const float4* xr = reinterpret_cast<const float4*>(x + (size_t)row * DDIM);
    uint2* xo = reinterpret_cast<uint2*>(g_xb + (size_t)row * DDIM);
    float s = 0.f;
#pragma unroll
    for (int k = 0; k < 4; k++) {
        int idx = lane + k * 32;
        float4 v = xr[idx];
        s += v.x * v.x + v.y * v.y + v.z * v.z + v.w * v.w;
        __nv_bfloat162 p0 = __float22bfloat162_rn(make_float2(v.x, v.y));
        __nv_bfloat162 p1 = __float22bfloat162_rn(make_float2(v.z, v.w));
        uint2 o;
        o.x = *reinterpret_cast<uint32_t*>(&p0);
        o.y = *reinterpret_cast<uint32_t*>(&p1);
        xo[idx] = o;
    }
#pragma unroll
    for (int o = 16; o; o >>= 1) s += __shfl_xor_sync(0xffffffffu, s, o);
    if (lane == 0) g_norms[row] = s;
}

// ---------------------------------------------------------------------------
// Dist: 128x128 CTA tile, 8 warps x (64x32), BK=64, 3-stage ring, 1 bar/chunk
// ---------------------------------------------------------------------------
__global__ __launch_bounds__(256, 2) void dist_kernel(float* __restrict__ out) {
    extern __shared__ __align__(16) char sm[];

    int tid  = threadIdx.x;
    int lane = tid & 31;
    int wid  = tid >> 5;
    int wr   = wid >> 2;     // warp row 0..1 (64 rows)
    int wc   = wid & 3;      // warp col 0..3 (32 cols)

    // linear block id -> (bi, bj), bj <= bi
    int t  = blockIdx.x;
    int bi = (int)((sqrtf(8.0f * (float)t + 1.0f) - 1.0f) * 0.5f);
    while ((bi * (bi + 1)) / 2 > t)        bi--;
    while (((bi + 1) * (bi + 2)) / 2 <= t) bi++;
    int bj = t - (bi * (bi + 1)) / 2;
    int i0 = bi * BM;
    int j0 = bj * BN;

    const __nv_bfloat16* gA = g_xb + (size_t)i0 * DDIM;
    const __nv_bfloat16* gB = g_xb + (size_t)j0 * DDIM;

    float acc[4][4][4];
#pragma unroll
    for (int m = 0; m < 4; m++)
#pragma unroll
        for (int n = 0; n < 4; n++)
#pragma unroll
            for (int e = 0; e < 4; e++) acc[m][n][e] = 0.f;

    // cp.async coords: per array 128 rows x 128B = 1024 x 16B; 256 thr -> 4 iters
    int r_ld = tid >> 3;         // 0..31
    int q_ld = tid & 7;          // 16B segment within 128B row

    auto stageA = [&](int s) -> char* { return sm + s * STAGE_BYTES; };
    auto stageB = [&](int s) -> char* { return sm + s * STAGE_BYTES + STAGE_ELEMS * 2; };

    auto issue = [&](int c) {
        int s  = c % NSTAGE;
        int kb = c * BK;
        char* a = stageA(s);
        char* b = stageB(s);
#pragma unroll
        for (int it = 0; it < 4; it++) {
            int r = r_ld + it * 32;
            uint32_t da = (uint32_t)__cvta_generic_to_shared(
                a + (r * LDSW + q_ld * 8) * 2);
            CP_ASYNC16(da, gA + (size_t)r * DDIM + kb + q_ld * 8);
            uint32_t db = (uint32_t)__cvta_generic_to_shared(
                b + (r * LDSW + q_ld * 8) * 2);
            CP_ASYNC16(db, gB + (size_t)r * DDIM + kb + q_ld * 8);
        }
        asm volatile("cp.async.commit_group;");
    };

    // ldmatrix per-thread offsets
    // A x4 (m16 x k16): rows m_base + (lane&15), k half (lane>>4)*8
    int arow = wr * 64 + (lane & 15);
    int akof = (lane >> 4) * 8;
    // B x4 (n16 x k16): row n_base + ((lane>>4)&1)*8 + (lane&7), k + ((lane>>3)&1)*8
    int brow = wc * 32 + ((lane >> 4) & 1) * 8 + (lane & 7);
    int bkof = ((lane >> 3) & 1) * 8;

    issue(0);
    issue(1);

    for (int c = 0; c < NCH; c++) {
        if (c + 1 < NCH) {
            asm volatile("cp.async.wait_group 1;");
        } else {
            asm volatile("cp.async.wait_group 0;");
        }
        __syncthreads();
        // Safe: stage (c+2)%3 was last read in iteration c-1, separated by
        // the barrier above.
        if (c + 2 < NCH) issue(c + 2);

        int s = c % NSTAGE;
        uint32_t aBase = (uint32_t)__cvta_generic_to_shared(stageA(s));
        uint32_t bBase = (uint32_t)__cvta_generic_to_shared(stageB(s));
#pragma unroll
        for (int ks = 0; ks < 4; ks++) {
            uint32_t afr[4][4], bfr[2][4];
#pragma unroll
            for (int mi = 0; mi < 4; mi++) {
                uint32_t ad = aBase +
                    (uint32_t)(((arow + mi * 16) * LDSW + ks * 16 + akof) * 2);
                LDSM_X4(afr[mi], ad);
            }
#pragma unroll
            for (int p = 0; p < 2; p++) {
                uint32_t bd = bBase +
                    (uint32_t)(((brow + p * 16) * LDSW + ks * 16 + bkof) * 2);
                LDSM_X4(bfr[p], bd);
            }
#pragma unroll
            for (int mi = 0; mi < 4; mi++)
#pragma unroll
                for (int p = 0; p < 2; p++) {
                    MMA16816(acc[mi][2 * p],     afr[mi], bfr[p][0], bfr[p][1]);
                    MMA16816(acc[mi][2 * p + 1], afr[mi], bfr[p][2], bfr[p][3]);
                }
        }
    }

    // Epilogue: c-frag map: rows trow, trow+8; cols tcol, tcol+1
    int trow = lane >> 2;
    int tcol = (lane & 3) * 2;
#pragma unroll
    for (int mi = 0; mi < 4; mi++) {
#pragma unroll
        for (int half = 0; half < 2; half++) {
            int i = i0 + wr * 64 + mi * 16 + half * 8 + trow;
            float ni_ = g_norms[i];
            int ib = (i * (i - 1)) >> 1;
#pragma unroll
            for (int nj = 0; nj < 4; nj++) {
                int j = j0 + wc * 32 + nj * 8 + tcol;
                float c0 = acc[mi][nj][half * 2 + 0];
                float c1 = acc[mi][nj][half * 2 + 1];
                if (j < i)
                    out[ib + j] =
                        sqrtf(fmaxf(ni_ + g_norms[j] - 2.0f * c0, 0.0f));
                if (j + 1 < i)
                    out[ib + j + 1] =
                        sqrtf(fmaxf(ni_ + g_norms[j + 1] - 2.0f * c1, 0.0f));
            }
        }
    }
}

extern "C" void kernel_launch(void* const* d_in, const int* in_sizes, int n_in,
                              void* d_out, int out_size) {
    const float* x = (const float*)d_in[0];
    float* out = (float*)d_out;
    (void)in_sizes; (void)n_in; (void)out_size;

    prep_kernel<<<NROWS / 8, 256>>>(x);

    cudaFuncSetAttribute(dist_kernel, cudaFuncAttributeMaxDynamicSharedMemorySize,
                         SMEM_TOTAL);
    dist_kernel<<<NBLK, 256, SMEM_TOTAL>>>(out);
}